// round 12
// baseline (speedup 1.0000x reference)
#include <cuda_runtime.h>

// SSIM loss, fused separable 11x11 Gaussian, B=64, H=W=512.
// R12: attack stage-C L1 redundancy: 4-pair units (10-entry window, 2.1x
//      re-read vs 3.4x) + TH=32 (stage C = exactly 1 unit/thread, no partial
//      tiles, better halo ratio). Stage B direct-from-GMEM (R11), 4 CTAs/SM.

#define BATCH 64
#define IMG_H 512
#define IMG_W 512
#define TH 32
#define HALO 5
#define NCP 38                // pairs per padded row (cols 64*tx-6 .. 64*tx+69)
#define THREADS 256
#define TILES_X 8
#define TILES_Y 16
#define NBLOCKS (BATCH * TILES_X * TILES_Y)   // 8192

#define V_BYTES   (TH * NCP * 32)    // 38912
#define SMEM_BYTES V_BYTES           // 4 CTAs/SM: 155.6KB smem, regs<=64

#define NSLOTS 32
#define SLOT_STRIDE 16

typedef unsigned long long u64;

// Gaussian(ks=11, sigma=1.5), normalized.
#define W0 0.00102838f
#define W1 0.00759876f
#define W2 0.03600077f
#define W3 0.10936069f
#define W4 0.21300553f
#define W5 0.26601172f
__device__ __constant__ float c_w[11] = {W0,W1,W2,W3,W4,W5,W4,W3,W2,W1,W0};

__device__ double g_slots[NSLOTS * SLOT_STRIDE];   // static zero-init

__device__ __forceinline__ unsigned smem_u32(const void* p) {
    unsigned r;
    asm("{ .reg .u64 t; cvta.to.shared.u64 t, %1; cvt.u32.u64 %0, t; }"
        : "=r"(r) : "l"(p));
    return r;
}
// Fold byte-address bits [7:9] into [4:6]; conflict-free for 32B-stride
// stores (stage B) and 32B-unit window reads (stage C). Involution.
// Sub-offsets inside a 32B unit are applied via XOR (swz(u+16)==swz(u)^16).
__device__ __forceinline__ unsigned swz(unsigned a) {
    return a ^ ((a >> 3) & 0x70u);
}
__device__ __forceinline__ u64 pack2(float lo, float hi) {
    u64 r; asm("mov.b64 %0, {%1,%2};" : "=l"(r) : "f"(lo), "f"(hi)); return r;
}
__device__ __forceinline__ void unpack2(u64 v, float& a, float& b) {
    asm("mov.b64 {%0,%1}, %2;" : "=f"(a), "=f"(b) : "l"(v));
}
__device__ __forceinline__ u64 swap2(u64 v) {
    u64 r;
    asm("{ .reg .b32 lo, hi; mov.b64 {lo,hi}, %1; mov.b64 %0, {hi,lo}; }"
        : "=l"(r) : "l"(v));
    return r;
}
__device__ __forceinline__ u64 fma2(u64 a, u64 b, u64 c) {
    u64 d; asm("fma.rn.f32x2 %0, %1, %2, %3;" : "=l"(d) : "l"(a), "l"(b), "l"(c));
    return d;
}
__device__ __forceinline__ u64 mul2(u64 a, u64 b) {
    u64 d; asm("mul.rn.f32x2 %0, %1, %2;" : "=l"(d) : "l"(a), "l"(b)); return d;
}
__device__ __forceinline__ u64 add2(u64 a, u64 b) {
    u64 d; asm("add.rn.f32x2 %0, %1, %2;" : "=l"(d) : "l"(a), "l"(b)); return d;
}
__device__ __forceinline__ u64 ldg64(const float* p) {
    u64 r; asm volatile("ld.global.nc.b64 %0, [%1];" : "=l"(r) : "l"(p));
    return r;
}
__device__ __forceinline__ void lds128(unsigned addr, u64& a, u64& b) {
    asm volatile("ld.shared.v2.b64 {%0,%1}, [%2];" : "=l"(a), "=l"(b) : "r"(addr));
}
__device__ __forceinline__ void sts128(unsigned addr, u64 a, u64 b) {
    asm volatile("st.shared.v2.b64 [%0], {%1,%2};" :: "r"(addr), "l"(a), "l"(b));
}

__global__ void ssim_zero_k() {
    g_slots[threadIdx.x * SLOT_STRIDE] = 0.0;
}

__global__ void ssim_finalize_k(float* out) {
    int t = threadIdx.x;
    double v = g_slots[t * SLOT_STRIDE];
    #pragma unroll
    for (int off = 16; off > 0; off >>= 1)
        v += __shfl_down_sync(0xFFFFFFFFu, v, off);
    if (t == 0)
        out[0] = (float)(1.0 - v / ((double)BATCH * IMG_H * IMG_W));
}

// Horizontal 11-tap conv, EVEN-aligned pairs: out pair q from window units
// q..q+6 (win[0..6]).  out = ACC + swap(ACCS):
//   ACC  = sum_{i=1..5} splat(w[2i-1]) * win[i]
//   ACCS = (0,w0)*win[0] + sum_{i=1..5}(w[2i-2],w[2i])*win[i] + (w10,0)*win[6]
__device__ __forceinline__ u64 hconv_e(const u64* win, const u64* wS, const u64* wD) {
    u64 acc = 0, accS = 0;
    #pragma unroll
    for (int i = 1; i <= 5; i++) {
        acc  = fma2(wS[i - 1], win[i], acc);
        accS = fma2(wD[i],     win[i], accS);
    }
    accS = fma2(wD[0], win[0], accS);
    accS = fma2(wD[6], win[6], accS);
    return add2(acc, swap2(accS));
}

__global__ __launch_bounds__(THREADS, 4)
void ssim_main_k(const float* __restrict__ x, const float* __restrict__ y) {
    extern __shared__ float smem[];
    const unsigned vb = smem_u32(smem);

    const int tid = threadIdx.x;
    const int blk = blockIdx.x;
    const int b  = blk >> 7;
    const int t  = blk & 127;
    const int ty = t >> 3;
    const int tx = t & 7;
    const int gx0 = tx * 64 - 6;          // EVEN left edge (covers halo -5)
    const int gy0 = ty * TH - HALO;

    const float* __restrict__ xb = x + (size_t)b * IMG_H * IMG_W;
    const float* __restrict__ yb = y + (size_t)b * IMG_H * IMG_W;

    // ---- Stage B: vertical conv {x, y, x2+y2, xy} straight from GMEM.
    //      304 items = 8 strips x 38 col-pairs, 4-row strips, 14 rows each.
    {
        u64 w2[6];   // symmetric: w[k] == w[10-k]
        #pragma unroll
        for (int k = 0; k < 6; k++) w2[k] = pack2(c_w[k], c_w[k]);

        const bool interior = (gx0 >= 0) & (gx0 + 2 * NCP <= IMG_W) &
                              (gy0 >= 0) & (gy0 + TH + 10 <= IMG_H);

        for (int e = tid; e < 8 * NCP; e += THREADS) {
            int rs = e / NCP;
            int cp = e - rs * NCP;
            int r0 = rs * 4;

            u64 s0[4] = {0,0,0,0};
            u64 s1[4] = {0,0,0,0};
            u64 s2[4] = {0,0,0,0};
            u64 s3[4] = {0,0,0,0};

            if (interior) {
                const float* xp = xb + (size_t)(gy0 + r0) * IMG_W + (gx0 + 2 * cp);
                const float* yp = yb + (size_t)(gy0 + r0) * IMG_W + (gx0 + 2 * cp);
                #pragma unroll
                for (int j = 0; j < 14; j++) {
                    u64 a  = ldg64(xp + j * IMG_W);
                    u64 bb = ldg64(yp + j * IMG_W);
                    u64 ab = mul2(a, bb);
                    u64 qq = fma2(a, a, mul2(bb, bb));
                    #pragma unroll
                    for (int tt = 0; tt < 4; tt++) {
                        int k = j - tt;
                        if (k >= 0 && k <= 10) {
                            u64 wk = w2[(k <= 5) ? k : 10 - k];
                            s0[tt] = fma2(wk, a,  s0[tt]);
                            s1[tt] = fma2(wk, bb, s1[tt]);
                            s2[tt] = fma2(wk, qq, s2[tt]);
                            s3[tt] = fma2(wk, ab, s3[tt]);
                        }
                    }
                }
            } else {
                int c0 = gx0 + 2 * cp;
                #pragma unroll
                for (int j = 0; j < 14; j++) {
                    int gy = gy0 + r0 + j;
                    float x0 = 0.f, x1 = 0.f, y0 = 0.f, y1 = 0.f;
                    if ((unsigned)gy < IMG_H) {
                        size_t rowb = (size_t)gy * IMG_W;
                        if ((unsigned)c0 < IMG_W) { x0 = xb[rowb + c0]; y0 = yb[rowb + c0]; }
                        if ((unsigned)(c0 + 1) < IMG_W) { x1 = xb[rowb + c0 + 1]; y1 = yb[rowb + c0 + 1]; }
                    }
                    u64 a  = pack2(x0, x1);
                    u64 bb = pack2(y0, y1);
                    u64 ab = mul2(a, bb);
                    u64 qq = fma2(a, a, mul2(bb, bb));
                    #pragma unroll
                    for (int tt = 0; tt < 4; tt++) {
                        int k = j - tt;
                        if (k >= 0 && k <= 10) {
                            u64 wk = w2[(k <= 5) ? k : 10 - k];
                            s0[tt] = fma2(wk, a,  s0[tt]);
                            s1[tt] = fma2(wk, bb, s1[tt]);
                            s2[tt] = fma2(wk, qq, s2[tt]);
                            s3[tt] = fma2(wk, ab, s3[tt]);
                        }
                    }
                }
            }
            #pragma unroll
            for (int tt = 0; tt < 4; tt++) {
                unsigned u = (unsigned)(((r0 + tt) * NCP + cp) << 5);
                unsigned su = vb + swz(u);
                sts128(su,       s0[tt], s1[tt]);   // v01 at swz(u)
                sts128(su ^ 16u, s2[tt], s3[tt]);   // v23 at swz(u)^16
            }
        }
    }
    __syncthreads();

    // ---- Stage C: 256 units = 32 rows x 8 qblocks, 4 output pairs each,
    //      10-entry window, two passes (v01 then v23). ----
    float lsum = 0.f;
    {
        u64 wS[5], wD[7];
        #pragma unroll
        for (int i = 1; i <= 5; i++) wS[i - 1] = pack2(c_w[2 * i - 1], c_w[2 * i - 1]);
        wD[0] = pack2(0.f, c_w[0]);
        #pragma unroll
        for (int i = 1; i <= 5; i++) wD[i] = pack2(c_w[2 * i - 2], c_w[2 * i]);
        wD[6] = pack2(c_w[10], 0.f);

        const u64 c1_2  = pack2(1e-4f, 1e-4f);
        const u64 c2_2  = pack2(9e-4f, 9e-4f);
        const u64 eps2  = pack2(1e-12f, 1e-12f);
        const u64 n1_2  = pack2(-1.f, -1.f);
        const u64 two_2 = pack2(2.f, 2.f);

        const int r  = tid >> 3;         // 0..31
        const int qb = tid & 7;          // output pairs 4qb..4qb+3
        const unsigned ub = (unsigned)((r * NCP + 4 * qb) << 5);

        u64 pa[10], pb[10];
        // pass 1: v01 window -> mu_x, mu_y
        #pragma unroll
        for (int i = 0; i < 10; i++)
            lds128(vb + swz(ub + (unsigned)(i << 5)), pa[i], pb[i]);

        u64 muxy[4], S[4];
        #pragma unroll
        for (int o = 0; o < 4; o++) {
            u64 mx = hconv_e(pa + o, wS, wD);
            u64 my = hconv_e(pb + o, wS, wD);
            muxy[o] = mul2(mx, my);
            S[o]    = fma2(mx, mx, mul2(my, my));
        }

        // pass 2: v23 window (sub-offset via XOR)
        #pragma unroll
        for (int i = 0; i < 10; i++)
            lds128(vb + (swz(ub + (unsigned)(i << 5)) ^ 16u), pa[i], pb[i]);

        #pragma unroll
        for (int o = 0; o < 4; o++) {
            u64 m2 = hconv_e(pa + o, wS, wD);
            u64 m3 = hconv_e(pb + o, wS, wD);
            u64 B1 = add2(S[o], c1_2);
            u64 B2 = fma2(n1_2, S[o], add2(m2, c2_2));
            u64 A1 = fma2(two_2, muxy[o], c1_2);
            u64 A2 = fma2(two_2, fma2(n1_2, muxy[o], m3), c2_2);
            u64 num = mul2(A1, A2);
            u64 den = fma2(B1, B2, eps2);
            float nl, nh, dl, dh;
            unpack2(num, nl, nh);
            unpack2(den, dl, dh);
            lsum += __fdividef(nl, dl) + __fdividef(nh, dh);
        }
    }

    // ---- Block reduction (8 warps) ----
    #pragma unroll
    for (int off = 16; off > 0; off >>= 1)
        lsum += __shfl_down_sync(0xFFFFFFFFu, lsum, off);

    __syncthreads();
    float* red = smem;
    int warp = tid >> 5, lane = tid & 31;
    if (lane == 0) red[warp] = lsum;
    __syncthreads();
    if (warp == 0) {
        float v = (lane < (THREADS / 32)) ? red[lane] : 0.f;
        #pragma unroll
        for (int off = 4; off > 0; off >>= 1)
            v += __shfl_down_sync(0xFFFFFFFFu, v, off);
        if (lane == 0)
            atomicAdd(&g_slots[(blockIdx.x & (NSLOTS - 1)) * SLOT_STRIDE],
                      (double)v);
    }
}

extern "C" void kernel_launch(void* const* d_in, const int* in_sizes, int n_in,
                              void* d_out, int out_size) {
    (void)in_sizes; (void)n_in; (void)out_size;
    const float* x = (const float*)d_in[0];
    const float* y = (const float*)d_in[1];
    float* out = (float*)d_out;

    static bool attr_set = false;
    if (!attr_set) {
        cudaFuncSetAttribute(ssim_main_k,
                             cudaFuncAttributeMaxDynamicSharedMemorySize,
                             SMEM_BYTES);
        attr_set = true;
    }

    ssim_main_k<<<NBLOCKS, THREADS, SMEM_BYTES>>>(x, y);
    ssim_finalize_k<<<1, 32>>>(out);
    ssim_zero_k<<<1, NSLOTS>>>();
}

// round 13
// speedup vs baseline: 1.2133x; 1.2133x over previous
#include <cuda_runtime.h>

// SSIM loss, fused separable 11x11 Gaussian, B=64, H=W=512.
// R13: R12's 4-pair stage-C units (37% fewer stage-C LDS bytes) WITHOUT the
//      register blowup: scatter-form scalar conv with literal weights
//      (FFMA-imm, rt=1, zero weight regs; window entries die immediately).
//      TH=32, stage B direct-from-GMEM (R11), swizzled v layout, 4 CTAs/SM.

#define BATCH 64
#define IMG_H 512
#define IMG_W 512
#define TH 32
#define HALO 5
#define NCP 38                // pairs per padded row (cols 64*tx-6 .. 64*tx+69)
#define THREADS 256
#define TILES_X 8
#define TILES_Y 16
#define NBLOCKS (BATCH * TILES_X * TILES_Y)   // 8192

#define V_BYTES   (TH * NCP * 32)    // 38912
#define SMEM_BYTES V_BYTES           // 4 CTAs/SM (155.6KB smem, regs<=64)

#define NSLOTS 32
#define SLOT_STRIDE 16

typedef unsigned long long u64;

// Gaussian(ks=11, sigma=1.5), normalized.
#define W0 0.00102838f
#define W1 0.00759876f
#define W2 0.03600077f
#define W3 0.10936069f
#define W4 0.21300553f
#define W5 0.26601172f
__device__ __constant__ float c_w[11] = {W0,W1,W2,W3,W4,W5,W4,W3,W2,W1,W0};

// Compile-time weight lookup (folds to an immediate in unrolled loops).
#define CWK(k) ((k)==0?W0:(k)==1?W1:(k)==2?W2:(k)==3?W3:(k)==4?W4: \
                (k)==5?W5:(k)==6?W4:(k)==7?W3:(k)==8?W2:(k)==9?W1:W0)

__device__ double g_slots[NSLOTS * SLOT_STRIDE];   // static zero-init

__device__ __forceinline__ unsigned smem_u32(const void* p) {
    unsigned r;
    asm("{ .reg .u64 t; cvta.to.shared.u64 t, %1; cvt.u32.u64 %0, t; }"
        : "=r"(r) : "l"(p));
    return r;
}
// Fold byte-address bits [7:9] into [4:6]; conflict-free for 32B-stride
// stores (stage B) and 32B-unit window reads (stage C). Involution.
// Sub-offsets inside a 32B unit via XOR (swz(u+16)==swz(u)^16).
__device__ __forceinline__ unsigned swz(unsigned a) {
    return a ^ ((a >> 3) & 0x70u);
}
__device__ __forceinline__ u64 pack2(float lo, float hi) {
    u64 r; asm("mov.b64 %0, {%1,%2};" : "=l"(r) : "f"(lo), "f"(hi)); return r;
}
__device__ __forceinline__ u64 fma2(u64 a, u64 b, u64 c) {
    u64 d; asm("fma.rn.f32x2 %0, %1, %2, %3;" : "=l"(d) : "l"(a), "l"(b), "l"(c));
    return d;
}
__device__ __forceinline__ u64 mul2(u64 a, u64 b) {
    u64 d; asm("mul.rn.f32x2 %0, %1, %2;" : "=l"(d) : "l"(a), "l"(b)); return d;
}
__device__ __forceinline__ u64 ldg64(const float* p) {
    u64 r; asm volatile("ld.global.nc.b64 %0, [%1];" : "=l"(r) : "l"(p));
    return r;
}
__device__ __forceinline__ float4 lds128f(unsigned addr) {
    float4 q;
    asm volatile("ld.shared.v4.f32 {%0,%1,%2,%3}, [%4];"
                 : "=f"(q.x), "=f"(q.y), "=f"(q.z), "=f"(q.w) : "r"(addr));
    return q;
}
__device__ __forceinline__ void sts128(unsigned addr, u64 a, u64 b) {
    asm volatile("st.shared.v2.b64 [%0], {%1,%2};" :: "r"(addr), "l"(a), "l"(b));
}

__global__ void ssim_zero_k() {
    g_slots[threadIdx.x * SLOT_STRIDE] = 0.0;
}

__global__ void ssim_finalize_k(float* out) {
    int t = threadIdx.x;
    double v = g_slots[t * SLOT_STRIDE];
    #pragma unroll
    for (int off = 16; off > 0; off >>= 1)
        v += __shfl_down_sync(0xFFFFFFFFu, v, off);
    if (t == 0)
        out[0] = (float)(1.0 - v / ((double)BATCH * IMG_H * IMG_W));
}

__global__ __launch_bounds__(THREADS, 4)
void ssim_main_k(const float* __restrict__ x, const float* __restrict__ y) {
    extern __shared__ float smem[];
    const unsigned vb = smem_u32(smem);

    const int tid = threadIdx.x;
    const int blk = blockIdx.x;
    const int b  = blk >> 7;
    const int t  = blk & 127;
    const int ty = t >> 3;
    const int tx = t & 7;
    const int gx0 = tx * 64 - 6;          // EVEN left edge (covers halo -5)
    const int gy0 = ty * TH - HALO;

    const float* __restrict__ xb = x + (size_t)b * IMG_H * IMG_W;
    const float* __restrict__ yb = y + (size_t)b * IMG_H * IMG_W;

    // ---- Stage B: vertical conv {x, y, x2+y2, xy} straight from GMEM.
    //      304 items = 8 strips x 38 col-pairs, 4-row strips, 14 rows each.
    {
        u64 w2[6];   // symmetric: w[k] == w[10-k]
        #pragma unroll
        for (int k = 0; k < 6; k++) w2[k] = pack2(c_w[k], c_w[k]);

        const bool interior = (gx0 >= 0) & (gx0 + 2 * NCP <= IMG_W) &
                              (gy0 >= 0) & (gy0 + TH + 10 <= IMG_H);

        for (int e = tid; e < 8 * NCP; e += THREADS) {
            int rs = e / NCP;
            int cp = e - rs * NCP;
            int r0 = rs * 4;

            u64 s0[4] = {0,0,0,0};
            u64 s1[4] = {0,0,0,0};
            u64 s2[4] = {0,0,0,0};
            u64 s3[4] = {0,0,0,0};

            if (interior) {
                const float* xp = xb + (size_t)(gy0 + r0) * IMG_W + (gx0 + 2 * cp);
                const float* yp = yb + (size_t)(gy0 + r0) * IMG_W + (gx0 + 2 * cp);
                #pragma unroll
                for (int j = 0; j < 14; j++) {
                    u64 a  = ldg64(xp + j * IMG_W);
                    u64 bb = ldg64(yp + j * IMG_W);
                    u64 ab = mul2(a, bb);
                    u64 qq = fma2(a, a, mul2(bb, bb));
                    #pragma unroll
                    for (int tt = 0; tt < 4; tt++) {
                        int k = j - tt;
                        if (k >= 0 && k <= 10) {
                            u64 wk = w2[(k <= 5) ? k : 10 - k];
                            s0[tt] = fma2(wk, a,  s0[tt]);
                            s1[tt] = fma2(wk, bb, s1[tt]);
                            s2[tt] = fma2(wk, qq, s2[tt]);
                            s3[tt] = fma2(wk, ab, s3[tt]);
                        }
                    }
                }
            } else {
                int c0 = gx0 + 2 * cp;
                #pragma unroll
                for (int j = 0; j < 14; j++) {
                    int gy = gy0 + r0 + j;
                    float x0 = 0.f, x1 = 0.f, y0 = 0.f, y1 = 0.f;
                    if ((unsigned)gy < IMG_H) {
                        size_t rowb = (size_t)gy * IMG_W;
                        if ((unsigned)c0 < IMG_W) { x0 = xb[rowb + c0]; y0 = yb[rowb + c0]; }
                        if ((unsigned)(c0 + 1) < IMG_W) { x1 = xb[rowb + c0 + 1]; y1 = yb[rowb + c0 + 1]; }
                    }
                    u64 a  = pack2(x0, x1);
                    u64 bb = pack2(y0, y1);
                    u64 ab = mul2(a, bb);
                    u64 qq = fma2(a, a, mul2(bb, bb));
                    #pragma unroll
                    for (int tt = 0; tt < 4; tt++) {
                        int k = j - tt;
                        if (k >= 0 && k <= 10) {
                            u64 wk = w2[(k <= 5) ? k : 10 - k];
                            s0[tt] = fma2(wk, a,  s0[tt]);
                            s1[tt] = fma2(wk, bb, s1[tt]);
                            s2[tt] = fma2(wk, qq, s2[tt]);
                            s3[tt] = fma2(wk, ab, s3[tt]);
                        }
                    }
                }
            }
            #pragma unroll
            for (int tt = 0; tt < 4; tt++) {
                unsigned u = (unsigned)(((r0 + tt) * NCP + cp) << 5);
                unsigned su = vb + swz(u);
                sts128(su,       s0[tt], s1[tt]);   // v01 at swz(u)
                sts128(su ^ 16u, s2[tt], s3[tt]);   // v23 at swz(u)^16
            }
        }
    }
    __syncthreads();

    // ---- Stage C: 256 units = 32 rows x 8 qblocks, 8 output cols each.
    //      Scatter-form scalar conv, FFMA-imm weights, streamed window.
    //      Window entries i=0..9 hold input cols j=2i, 2i+1 (relative);
    //      output col c uses taps j = c+1 .. c+11 -> weight CWK(j-1-c).
    float lsum = 0.f;
    {
        const int r  = tid >> 3;         // 0..31
        const int qb = tid & 7;          // output cols 8qb .. 8qb+7
        const unsigned ub = (unsigned)((r * NCP + 4 * qb) << 5);

        float mx[8], my[8];
        #pragma unroll
        for (int c = 0; c < 8; c++) { mx[c] = 0.f; my[c] = 0.f; }

        // pass 1: v01 (mu_x in .x/.y, mu_y in .z/.w)
        #pragma unroll
        for (int i = 0; i < 10; i++) {
            float4 q = lds128f(vb + swz(ub + (unsigned)(i << 5)));
            #pragma unroll
            for (int h = 0; h < 2; h++) {
                const int jj = 2 * i + h;
                const float fa = h ? q.y : q.x;
                const float fb = h ? q.w : q.z;
                #pragma unroll
                for (int c = 0; c < 8; c++) {
                    const int k = jj - 1 - c;
                    if (k >= 0 && k <= 10) {
                        mx[c] = fmaf(CWK(k), fa, mx[c]);
                        my[c] = fmaf(CWK(k), fb, my[c]);
                    }
                }
            }
        }
        float muxy[8], S[8];
        #pragma unroll
        for (int c = 0; c < 8; c++) {
            muxy[c] = mx[c] * my[c];
            S[c]    = fmaf(mx[c], mx[c], my[c] * my[c]);
        }

        // pass 2: v23 (conv(x^2+y^2) in .x/.y, conv(xy) in .z/.w)
        float m2[8], m3[8];
        #pragma unroll
        for (int c = 0; c < 8; c++) { m2[c] = 0.f; m3[c] = 0.f; }
        #pragma unroll
        for (int i = 0; i < 10; i++) {
            float4 q = lds128f(vb + (swz(ub + (unsigned)(i << 5)) ^ 16u));
            #pragma unroll
            for (int h = 0; h < 2; h++) {
                const int jj = 2 * i + h;
                const float fa = h ? q.y : q.x;
                const float fb = h ? q.w : q.z;
                #pragma unroll
                for (int c = 0; c < 8; c++) {
                    const int k = jj - 1 - c;
                    if (k >= 0 && k <= 10) {
                        m2[c] = fmaf(CWK(k), fa, m2[c]);
                        m3[c] = fmaf(CWK(k), fb, m3[c]);
                    }
                }
            }
        }

        const float C1 = 1e-4f, C2 = 9e-4f;
        #pragma unroll
        for (int c = 0; c < 8; c++) {
            float B1 = S[c] + C1;
            float B2 = (m2[c] - S[c]) + C2;
            float A1 = fmaf(2.f, muxy[c], C1);
            float A2 = fmaf(2.f, m3[c] - muxy[c], C2);
            lsum += __fdividef(A1 * A2, fmaf(B1, B2, 1e-12f));
        }
    }

    // ---- Block reduction (8 warps) ----
    #pragma unroll
    for (int off = 16; off > 0; off >>= 1)
        lsum += __shfl_down_sync(0xFFFFFFFFu, lsum, off);

    __syncthreads();
    float* red = smem;
    int warp = tid >> 5, lane = tid & 31;
    if (lane == 0) red[warp] = lsum;
    __syncthreads();
    if (warp == 0) {
        float v = (lane < (THREADS / 32)) ? red[lane] : 0.f;
        #pragma unroll
        for (int off = 4; off > 0; off >>= 1)
            v += __shfl_down_sync(0xFFFFFFFFu, v, off);
        if (lane == 0)
            atomicAdd(&g_slots[(blockIdx.x & (NSLOTS - 1)) * SLOT_STRIDE],
                      (double)v);
    }
}

extern "C" void kernel_launch(void* const* d_in, const int* in_sizes, int n_in,
                              void* d_out, int out_size) {
    (void)in_sizes; (void)n_in; (void)out_size;
    const float* x = (const float*)d_in[0];
    const float* y = (const float*)d_in[1];
    float* out = (float*)d_out;

    static bool attr_set = false;
    if (!attr_set) {
        cudaFuncSetAttribute(ssim_main_k,
                             cudaFuncAttributeMaxDynamicSharedMemorySize,
                             SMEM_BYTES);
        attr_set = true;
    }

    ssim_main_k<<<NBLOCKS, THREADS, SMEM_BYTES>>>(x, y);
    ssim_finalize_k<<<1, 32>>>(out);
    ssim_zero_k<<<1, NSLOTS>>>();
}

// round 14
// speedup vs baseline: 1.2187x; 1.0044x over previous
#include <cuda_runtime.h>
#include <cuda_fp16.h>

// SSIM loss, fused separable 11x11 Gaussian, B=64, H=W=512.
// R14: f16 v-array (all 4 planes in ONE 16B unit) -> stage C single-pass,
//      half the v STS/LDS bytes. Pad-based conflict-free layout (1 pad unit
//      per 4 -> 80B qb-stride, slots {0,80,32,112,64,16,96,48} mod 128).
//      Stage B direct-from-GMEM (R11), scatter FFMA-imm stage C (R13).

#define BATCH 64
#define IMG_H 512
#define IMG_W 512
#define TH 32
#define HALO 5
#define NCP 38                // col-pairs per padded row
#define THREADS 256
#define TILES_X 8
#define TILES_Y 16
#define NBLOCKS (BATCH * TILES_X * TILES_Y)   // 8192

#define VROW_B 768            // padded row stride: 48 units * 16B (6 x 128B)
#define SMEM_BYTES (TH * VROW_B)   // 24576 -> 4 CTAs/SM (reg-limited)

#define NSLOTS 32
#define SLOT_STRIDE 16

typedef unsigned long long u64;

// Gaussian(ks=11, sigma=1.5), normalized.
#define W0 0.00102838f
#define W1 0.00759876f
#define W2 0.03600077f
#define W3 0.10936069f
#define W4 0.21300553f
#define W5 0.26601172f
__device__ __constant__ float c_w[11] = {W0,W1,W2,W3,W4,W5,W4,W3,W2,W1,W0};

// Compile-time weight lookup (folds to FFMA immediates).
#define CWK(k) ((k)==0?W0:(k)==1?W1:(k)==2?W2:(k)==3?W3:(k)==4?W4: \
                (k)==5?W5:(k)==6?W4:(k)==7?W3:(k)==8?W2:(k)==9?W1:W0)

__device__ double g_slots[NSLOTS * SLOT_STRIDE];   // static zero-init

__device__ __forceinline__ unsigned smem_u32(const void* p) {
    unsigned r;
    asm("{ .reg .u64 t; cvta.to.shared.u64 t, %1; cvt.u32.u64 %0, t; }"
        : "=r"(r) : "l"(p));
    return r;
}
__device__ __forceinline__ u64 pack2(float lo, float hi) {
    u64 r; asm("mov.b64 %0, {%1,%2};" : "=l"(r) : "f"(lo), "f"(hi)); return r;
}
__device__ __forceinline__ void unpack2(u64 v, float& a, float& b) {
    asm("mov.b64 {%0,%1}, %2;" : "=f"(a), "=f"(b) : "l"(v));
}
__device__ __forceinline__ u64 fma2(u64 a, u64 b, u64 c) {
    u64 d; asm("fma.rn.f32x2 %0, %1, %2, %3;" : "=l"(d) : "l"(a), "l"(b), "l"(c));
    return d;
}
__device__ __forceinline__ u64 mul2(u64 a, u64 b) {
    u64 d; asm("mul.rn.f32x2 %0, %1, %2;" : "=l"(d) : "l"(a), "l"(b)); return d;
}
__device__ __forceinline__ u64 ldg64(const float* p) {
    u64 r; asm volatile("ld.global.nc.b64 %0, [%1];" : "=l"(r) : "l"(p));
    return r;
}
__device__ __forceinline__ uint4 lds128u(unsigned addr) {
    uint4 q;
    asm volatile("ld.shared.v4.b32 {%0,%1,%2,%3}, [%4];"
                 : "=r"(q.x), "=r"(q.y), "=r"(q.z), "=r"(q.w) : "r"(addr));
    return q;
}
__device__ __forceinline__ void sts128u(unsigned addr, unsigned a, unsigned b,
                                        unsigned c, unsigned d) {
    asm volatile("st.shared.v4.b32 [%0], {%1,%2,%3,%4};"
                 :: "r"(addr), "r"(a), "r"(b), "r"(c), "r"(d));
}
// pack a u64 f32x2 (lo,hi) into one f16x2 word
__device__ __forceinline__ unsigned f2h2(u64 v) {
    float lo, hi;
    unpack2(v, lo, hi);
    __half2 h = __floats2half2_rn(lo, hi);
    return *reinterpret_cast<unsigned*>(&h);
}
__device__ __forceinline__ float2 h22f2(unsigned u) {
    __half2 h = *reinterpret_cast<__half2*>(&u);
    return __half22float2(h);
}

__global__ void ssim_zero_k() {
    g_slots[threadIdx.x * SLOT_STRIDE] = 0.0;
}

__global__ void ssim_finalize_k(float* out) {
    int t = threadIdx.x;
    double v = g_slots[t * SLOT_STRIDE];
    #pragma unroll
    for (int off = 16; off > 0; off >>= 1)
        v += __shfl_down_sync(0xFFFFFFFFu, v, off);
    if (t == 0)
        out[0] = (float)(1.0 - v / ((double)BATCH * IMG_H * IMG_W));
}

__global__ __launch_bounds__(THREADS, 4)
void ssim_main_k(const float* __restrict__ x, const float* __restrict__ y) {
    extern __shared__ float smem[];
    const unsigned vb = smem_u32(smem);

    const int tid = threadIdx.x;
    const int blk = blockIdx.x;
    const int b  = blk >> 7;
    const int t  = blk & 127;
    const int ty = t >> 3;
    const int tx = t & 7;
    const int gx0 = tx * 64 - 6;          // EVEN left edge (covers halo -5)
    const int gy0 = ty * TH - HALO;

    const float* __restrict__ xb = x + (size_t)b * IMG_H * IMG_W;
    const float* __restrict__ yb = y + (size_t)b * IMG_H * IMG_W;

    // ---- Stage B: vertical conv {x, y, x2+y2, xy} straight from GMEM.
    //      304 items = 8 strips x 38 col-pairs, 4-row strips, 14 rows each.
    //      Output: one 16B f16 unit per (row, col-pair): (mux2|muy2|m2|m3).
    {
        u64 w2[6];   // symmetric: w[k] == w[10-k]
        #pragma unroll
        for (int k = 0; k < 6; k++) w2[k] = pack2(c_w[k], c_w[k]);

        const bool interior = (gx0 >= 0) & (gx0 + 2 * NCP <= IMG_W) &
                              (gy0 >= 0) & (gy0 + TH + 10 <= IMG_H);

        for (int e = tid; e < 8 * NCP; e += THREADS) {
            int rs = e / NCP;
            int cp = e - rs * NCP;
            int r0 = rs * 4;

            u64 s0[4] = {0,0,0,0};
            u64 s1[4] = {0,0,0,0};
            u64 s2[4] = {0,0,0,0};
            u64 s3[4] = {0,0,0,0};

            if (interior) {
                const float* xp = xb + (size_t)(gy0 + r0) * IMG_W + (gx0 + 2 * cp);
                const float* yp = yb + (size_t)(gy0 + r0) * IMG_W + (gx0 + 2 * cp);
                #pragma unroll
                for (int j = 0; j < 14; j++) {
                    u64 a  = ldg64(xp + j * IMG_W);
                    u64 bb = ldg64(yp + j * IMG_W);
                    u64 ab = mul2(a, bb);
                    u64 qq = fma2(a, a, mul2(bb, bb));
                    #pragma unroll
                    for (int tt = 0; tt < 4; tt++) {
                        int k = j - tt;
                        if (k >= 0 && k <= 10) {
                            u64 wk = w2[(k <= 5) ? k : 10 - k];
                            s0[tt] = fma2(wk, a,  s0[tt]);
                            s1[tt] = fma2(wk, bb, s1[tt]);
                            s2[tt] = fma2(wk, qq, s2[tt]);
                            s3[tt] = fma2(wk, ab, s3[tt]);
                        }
                    }
                }
            } else {
                int c0 = gx0 + 2 * cp;
                #pragma unroll
                for (int j = 0; j < 14; j++) {
                    int gy = gy0 + r0 + j;
                    float x0 = 0.f, x1 = 0.f, y0 = 0.f, y1 = 0.f;
                    if ((unsigned)gy < IMG_H) {
                        size_t rowb = (size_t)gy * IMG_W;
                        if ((unsigned)c0 < IMG_W) { x0 = xb[rowb + c0]; y0 = yb[rowb + c0]; }
                        if ((unsigned)(c0 + 1) < IMG_W) { x1 = xb[rowb + c0 + 1]; y1 = yb[rowb + c0 + 1]; }
                    }
                    u64 a  = pack2(x0, x1);
                    u64 bb = pack2(y0, y1);
                    u64 ab = mul2(a, bb);
                    u64 qq = fma2(a, a, mul2(bb, bb));
                    #pragma unroll
                    for (int tt = 0; tt < 4; tt++) {
                        int k = j - tt;
                        if (k >= 0 && k <= 10) {
                            u64 wk = w2[(k <= 5) ? k : 10 - k];
                            s0[tt] = fma2(wk, a,  s0[tt]);
                            s1[tt] = fma2(wk, bb, s1[tt]);
                            s2[tt] = fma2(wk, qq, s2[tt]);
                            s3[tt] = fma2(wk, ab, s3[tt]);
                        }
                    }
                }
            }
            // padded unit position: p = cp + cp/4 (1 pad per 4 units)
            const unsigned pcol = (unsigned)((cp + (cp >> 2)) << 4);
            #pragma unroll
            for (int tt = 0; tt < 4; tt++) {
                unsigned sa = vb + (unsigned)((r0 + tt) * VROW_B) + pcol;
                sts128u(sa, f2h2(s0[tt]), f2h2(s1[tt]), f2h2(s2[tt]), f2h2(s3[tt]));
            }
        }
    }
    __syncthreads();

    // ---- Stage C: 256 units = 32 rows x 8 qblocks, 8 output cols each.
    //      Single pass: each 16B unit holds all 4 planes. Scatter FFMA-imm.
    //      Entry i holds input cols j=2i,2i+1 (rel); output col c taps
    //      j=c+1..c+11 -> weight CWK(j-1-c).
    float lsum = 0.f;
    {
        const int r  = tid >> 3;         // 0..31
        const int qb = tid & 7;          // output cols 8qb .. 8qb+7
        // unit index 4qb+i -> padded p = 5qb + i + i/4 (exact: (4qb+i)>>2 = qb+i/4)
        const unsigned base = vb + (unsigned)(r * VROW_B) + (unsigned)(qb * 80);

        float mx[8], my[8], m2[8], m3[8];
        #pragma unroll
        for (int c = 0; c < 8; c++) { mx[c]=0.f; my[c]=0.f; m2[c]=0.f; m3[c]=0.f; }

        #pragma unroll
        for (int i = 0; i < 10; i++) {
            uint4 q = lds128u(base + (unsigned)((i + (i >> 2)) << 4));
            float2 fx = h22f2(q.x);
            float2 fy = h22f2(q.y);
            float2 f2 = h22f2(q.z);
            float2 f3 = h22f2(q.w);
            #pragma unroll
            for (int h = 0; h < 2; h++) {
                const int jj = 2 * i + h;
                const float va = h ? fx.y : fx.x;
                const float vb2 = h ? fy.y : fy.x;
                const float vc = h ? f2.y : f2.x;
                const float vd = h ? f3.y : f3.x;
                #pragma unroll
                for (int c = 0; c < 8; c++) {
                    const int k = jj - 1 - c;
                    if (k >= 0 && k <= 10) {
                        mx[c] = fmaf(CWK(k), va,  mx[c]);
                        my[c] = fmaf(CWK(k), vb2, my[c]);
                        m2[c] = fmaf(CWK(k), vc,  m2[c]);
                        m3[c] = fmaf(CWK(k), vd,  m3[c]);
                    }
                }
            }
        }

        const float C1 = 1e-4f, C2 = 9e-4f;
        #pragma unroll
        for (int c = 0; c < 8; c++) {
            float muxy = mx[c] * my[c];
            float S    = fmaf(mx[c], mx[c], my[c] * my[c]);
            float B1 = S + C1;
            float B2 = (m2[c] - S) + C2;
            float A1 = fmaf(2.f, muxy, C1);
            float A2 = fmaf(2.f, m3[c] - muxy, C2);
            lsum += __fdividef(A1 * A2, fmaf(B1, B2, 1e-12f));
        }
    }

    // ---- Block reduction (8 warps) ----
    #pragma unroll
    for (int off = 16; off > 0; off >>= 1)
        lsum += __shfl_down_sync(0xFFFFFFFFu, lsum, off);

    __syncthreads();
    float* red = smem;
    int warp = tid >> 5, lane = tid & 31;
    if (lane == 0) red[warp] = lsum;
    __syncthreads();
    if (warp == 0) {
        float v = (lane < (THREADS / 32)) ? red[lane] : 0.f;
        #pragma unroll
        for (int off = 4; off > 0; off >>= 1)
            v += __shfl_down_sync(0xFFFFFFFFu, v, off);
        if (lane == 0)
            atomicAdd(&g_slots[(blockIdx.x & (NSLOTS - 1)) * SLOT_STRIDE],
                      (double)v);
    }
}

extern "C" void kernel_launch(void* const* d_in, const int* in_sizes, int n_in,
                              void* d_out, int out_size) {
    (void)in_sizes; (void)n_in; (void)out_size;
    const float* x = (const float*)d_in[0];
    const float* y = (const float*)d_in[1];
    float* out = (float*)d_out;

    static bool attr_set = false;
    if (!attr_set) {
        cudaFuncSetAttribute(ssim_main_k,
                             cudaFuncAttributeMaxDynamicSharedMemorySize,
                             SMEM_BYTES);
        attr_set = true;
    }

    ssim_main_k<<<NBLOCKS, THREADS, SMEM_BYTES>>>(x, y);
    ssim_finalize_k<<<1, 32>>>(out);
    ssim_zero_k<<<1, NSLOTS>>>();
}